// round 1
// baseline (speedup 1.0000x reference)
#include <cuda_runtime.h>
#include <math.h>

// ---------------- problem constants ----------------
#define BB 64
#define PP 576
#define DD 768
#define NG 64
#define NN 65
#define NSTEPS 8

// ---------------- output layout (float32, concatenated in tuple order) ----
#define OFF_KEEP  0          // B*(P+1) = 36928
#define OFF_PKEEP 36928      // B*P     = 36864
#define OFF_GID   73792      // B*P
#define OFF_GS    110656     // B*P
#define OFF_DH    147520     // B*9*65*65 = 2433600
#define OFF_QH    2581120    // B*8*65*65 = 2163200
#define OFF_RT    4744320    // B*64*64   = 262144
#define OFF_AS    5006464
#define OFF_AST   5006465

// ---------------- scratch (static device globals; no allocation) ----------
__device__ float g_nodes[BB * NN * DD];        // 12.2 MB
__device__ float g_proj [BB * NN * DD];        // 12.2 MB
__device__ float g_gramp[BB * 3 * NN * NN];    // K-split partials
__device__ float g_gflow[BB * NG];
__device__ float g_auxsp[BB];
__device__ float g_auxst[BB];

// packed f32x2 FMA (FFMA2) — ptxas never emits this from C++; PTX only.
__device__ __forceinline__ void fma2(unsigned long long &acc, float a,
                                     unsigned long long b) {
    unsigned long long aa;
    asm("mov.b64 %0, {%1, %1};" : "=l"(aa) : "f"(a));
    asm("fma.rn.f32x2 %0, %1, %2, %0;" : "+l"(acc) : "l"(aa), "l"(b));
}

// ============ K1: group pooling -> nodes (B,65,768) =======================
// grid (65, B), block 192 (one float4 per thread)
__global__ void k_nodes(const float* __restrict__ tokens,
                        const float* __restrict__ cls) {
    int n = blockIdx.x, b = blockIdx.y, t = threadIdx.x;
    float4* dst = (float4*)&g_nodes[(b * NN + n) * DD];
    if (n == 0) {
        dst[t] = ((const float4*)&cls[b * DD])[t];
    } else {
        int g = n - 1, gr = g >> 3, gc = g & 7;
        float4 s = make_float4(0.f, 0.f, 0.f, 0.f);
#pragma unroll
        for (int rr = 0; rr < 3; rr++)
#pragma unroll
            for (int cc = 0; cc < 3; cc++) {
                int p = (gr * 3 + rr) * 24 + gc * 3 + cc;
                float4 v = ((const float4*)&tokens[(b * PP + p) * DD])[t];
                s.x += v.x; s.y += v.y; s.z += v.z; s.w += v.w;
            }
        const float inv9 = 1.f / 9.f;
        s.x *= inv9; s.y *= inv9; s.z *= inv9; s.w *= inv9;
        dst[t] = s;
    }
}

// ============ K2: proj = nodes(4160x768) @ W^T(768x768) ===================
// grid (65, 6), block 256; 64x128 tile, 4x8 per thread via FFMA2 pairs
__global__ void __launch_bounds__(256) k_gemm(const float* __restrict__ Wm) {
    __shared__ __align__(16) float As[32][64];
    __shared__ __align__(8)  float Bs[32][130];
    int bm = blockIdx.x * 64, bn = blockIdx.y * 128;
    int tid = threadIdx.x;
    int tx = tid & 15, ty = tid >> 4;
    unsigned long long acc[4][4];
#pragma unroll
    for (int i = 0; i < 4; i++)
#pragma unroll
        for (int j = 0; j < 4; j++) acc[i][j] = 0ull;

    for (int k0 = 0; k0 < DD; k0 += 32) {
        for (int t = tid; t < 512; t += 256) {
            int r = t >> 3, c = t & 7;
            float4 v = *(const float4*)&g_nodes[(bm + r) * DD + k0 + c * 4];
            As[c * 4 + 0][r] = v.x; As[c * 4 + 1][r] = v.y;
            As[c * 4 + 2][r] = v.z; As[c * 4 + 3][r] = v.w;
        }
        for (int t = tid; t < 1024; t += 256) {
            int r = t >> 3, c = t & 7;
            float4 v = *(const float4*)&Wm[(bn + r) * DD + k0 + c * 4];
            Bs[c * 4 + 0][r] = v.x; Bs[c * 4 + 1][r] = v.y;
            Bs[c * 4 + 2][r] = v.z; Bs[c * 4 + 3][r] = v.w;
        }
        __syncthreads();
#pragma unroll
        for (int kk = 0; kk < 32; kk++) {
            float4 a = *(const float4*)&As[kk][ty * 4];
            unsigned long long b0 = *(const unsigned long long*)&Bs[kk][tx * 2 + 0];
            unsigned long long b1 = *(const unsigned long long*)&Bs[kk][tx * 2 + 32];
            unsigned long long b2 = *(const unsigned long long*)&Bs[kk][tx * 2 + 64];
            unsigned long long b3 = *(const unsigned long long*)&Bs[kk][tx * 2 + 96];
            fma2(acc[0][0], a.x, b0); fma2(acc[0][1], a.x, b1);
            fma2(acc[0][2], a.x, b2); fma2(acc[0][3], a.x, b3);
            fma2(acc[1][0], a.y, b0); fma2(acc[1][1], a.y, b1);
            fma2(acc[1][2], a.y, b2); fma2(acc[1][3], a.y, b3);
            fma2(acc[2][0], a.z, b0); fma2(acc[2][1], a.z, b1);
            fma2(acc[2][2], a.z, b2); fma2(acc[2][3], a.z, b3);
            fma2(acc[3][0], a.w, b0); fma2(acc[3][1], a.w, b1);
            fma2(acc[3][2], a.w, b2); fma2(acc[3][3], a.w, b3);
        }
        __syncthreads();
    }
#pragma unroll
    for (int i = 0; i < 4; i++) {
        int m = bm + ty * 4 + i;
#pragma unroll
        for (int j = 0; j < 4; j++) {
            int n = bn + tx * 2 + j * 32;
            *(unsigned long long*)&g_proj[m * DD + n] = acc[i][j];
        }
    }
}

// ============ K3: Gram partials G = proj proj^T, K-split 3 ================
// grid (B, 3), block 169 (13x13 threads, 5x5 outputs each)
__global__ void k_gram() {
    __shared__ float S[64][65];
    int b = blockIdx.x, ks = blockIdx.y;
    int tid = threadIdx.x;
    int tx = tid % 13, ty = tid / 13;
    float acc[5][5];
#pragma unroll
    for (int i = 0; i < 5; i++)
#pragma unroll
        for (int j = 0; j < 5; j++) acc[i][j] = 0.f;

    for (int sub = 0; sub < 4; sub++) {
        int kb = ks * 256 + sub * 64;
        __syncthreads();
        for (int t = tid; t < 1040; t += 169) {
            int n = t / 16, c = t % 16;
            float4 v = *(const float4*)&g_proj[(b * NN + n) * DD + kb + c * 4];
            S[c * 4 + 0][n] = v.x; S[c * 4 + 1][n] = v.y;
            S[c * 4 + 2][n] = v.z; S[c * 4 + 3][n] = v.w;
        }
        __syncthreads();
        for (int kk = 0; kk < 64; kk++) {
            float av[5], bv[5];
#pragma unroll
            for (int i = 0; i < 5; i++) { av[i] = S[kk][ty * 5 + i]; bv[i] = S[kk][tx * 5 + i]; }
#pragma unroll
            for (int i = 0; i < 5; i++)
#pragma unroll
                for (int j = 0; j < 5; j++) acc[i][j] += av[i] * bv[j];
        }
    }
    float* gp = &g_gramp[(b * 3 + ks) * (NN * NN)];
#pragma unroll
    for (int i = 0; i < 5; i++)
#pragma unroll
        for (int j = 0; j < 5; j++)
            gp[(ty * 5 + i) * NN + (tx * 5 + j)] = acc[i][j];
}

// ============ K4: C0 = floor(exp(-(2-2*cos))) written into d_hist[:,0] ====
__global__ void k_c0(float* __restrict__ out) {
    __shared__ float invn[NN];
    int b = blockIdx.x, tid = threadIdx.x;
    const float* gp = &g_gramp[b * 3 * NN * NN];
    if (tid < NN) {
        int d = tid * NN + tid;
        float g = gp[d] + gp[NN * NN + d] + gp[2 * NN * NN + d];
        invn[tid] = 1.f / sqrtf(g);
    }
    __syncthreads();
    float* dh0 = out + OFF_DH + (size_t)b * 9 * NN * NN;
    for (int idx = tid; idx < NN * NN; idx += blockDim.x) {
        int i = idx / NN, j = idx % NN;
        float c;
        if (i == j) c = 0.f;
        else {
            float g = gp[idx] + gp[NN * NN + idx] + gp[2 * NN * NN + idx];
            float dot = g * invn[i] * invn[j];
            float d2 = fmaxf(2.f - 2.f * dot, 0.f);
            c = fmaxf(expf(-d2), 1e-4f);
        }
        dh0[idx] = c;
    }
}

// ============ K5: dynamics — 8 steps of (solve, flow, update) per batch ===
// grid 64, block 416. Gauss-Jordan on strictly diagonally-dominant system.
__global__ void __launch_bounds__(416) k_dyn(float* __restrict__ out) {
    __shared__ float sC[NN * 66];
    __shared__ float sA[NN * 67];
    __shared__ float sp[NN], sf[NN], sdeg[NN];
    __shared__ float red[512];
    int b = blockIdx.x, tid = threadIdx.x;
    float* dh = out + OFF_DH + (size_t)b * 9 * NN * NN;
    float* qh = out + OFF_QH + (size_t)b * 8 * NN * NN;

    for (int idx = tid; idx < NN * NN; idx += 416)
        sC[(idx / NN) * 66 + (idx % NN)] = dh[idx];
    float auxst = 0.f;

    for (int s = 0; s < NSTEPS; s++) {
        __syncthreads();
        if (tid < NN) {
            float d = 0.f;
            const float* row = &sC[tid * 66];
            for (int j = 0; j < NN; j++) d += row[j];
            sdeg[tid] = d;
        }
        __syncthreads();
        for (int idx = tid; idx < NN * 66; idx += 416) {
            int i = idx / 66, j = idx % 66;
            float v;
            if (j == 65)      v = (i == 0) ? 1.f : (-1.f / 64.f);
            else if (i == j)  v = sdeg[i] + 1e-4f;
            else              v = -sC[i * 66 + j];
            sA[i * 67 + j] = v;
        }
        __syncthreads();
        // Gauss-Jordan (no pivoting: strictly diagonally dominant)
        for (int k = 0; k < NN; k++) {
            if (tid < NN) sf[tid] = (tid == k) ? 0.f : sA[tid * 67 + k] / sA[k * 67 + k];
            __syncthreads();
            if (tid < 390) {
                int row = tid / 6, c0 = (tid % 6) * 11;
                if (row != k) {
                    float f = sf[row];
                    float* ar = &sA[row * 67 + c0];
                    const float* pr = &sA[k * 67 + c0];
#pragma unroll
                    for (int jj = 0; jj < 11; jj++) ar[jj] -= f * pr[jj];
                }
            }
            __syncthreads();
        }
        if (tid < NN) sp[tid] = sA[tid * 67 + 65] / sA[tid * 67 + tid];
        __syncthreads();
        if (s == NSTEPS - 1 && tid < NG) {   // group flow from LAST step's flow
            int i = tid + 1;
            float acc = 0.f, pi = sp[i];
            for (int j = 0; j < NN; j++) acc += fabsf(sC[i * 66 + j] * (pi - sp[j]));
            g_gflow[b * NG + tid] = acc;
        }
        __syncthreads();
        float* dhs = dh + (size_t)(s + 1) * NN * NN;
        float* qhs = qh + (size_t)s * NN * NN;
        for (int idx = tid; idx < NN * NN; idx += 416) {
            int i = idx / NN, j = idx % NN;
            float c = sC[i * 66 + j];
            float fl = c * (sp[i] - sp[j]);
            qhs[idx] = fl;
            float a = fabsf(fl);
            float r = a / (1.f + a);
            float cn = c + 0.1f * (r - 0.1f * c);
            cn = fmaxf(cn, 0.f);
            cn = (i == j) ? 0.f : fmaxf(cn, 1e-4f);
            auxst += fabsf(cn - c);
            sC[i * 66 + j] = cn;
            dhs[idx] = cn;
        }
    }
    __syncthreads();
    // aux_sparse: interior sum of final C
    float asp = 0.f;
    for (int idx = tid; idx < NN * NN; idx += 416) {
        int i = idx / NN, j = idx % NN;
        if (i >= 1 && j >= 1) asp += sC[i * 66 + j];
    }
    red[tid] = asp; __syncthreads();
    for (int st = 256; st >= 1; st >>= 1) {
        if (tid < st && tid + st < 416) red[tid] += red[tid + st];
        __syncthreads();
    }
    if (tid == 0) g_auxsp[b] = red[0];
    __syncthreads();
    red[tid] = auxst; __syncthreads();
    for (int st = 256; st >= 1; st >>= 1) {
        if (tid < st && tid + st < 416) red[tid] += red[tid + st];
        __syncthreads();
    }
    if (tid == 0) g_auxst[b] = red[0];
    __syncthreads();
    // routing: normalized interior rows of final C
    if (tid < NG) {
        int i = tid + 1;
        float rs = 0.f;
        for (int j = 1; j < NN; j++) rs += sC[i * 66 + j];
        red[tid] = fmaxf(rs, 1e-6f);
    }
    __syncthreads();
    float* rt = out + OFF_RT + (size_t)b * NG * NG;
    for (int idx = tid; idx < NG * NG; idx += 416) {
        int i = idx / NG, j = idx % NG;
        rt[idx] = sC[(i + 1) * 66 + (j + 1)] / red[i];
    }
}

// ============ K6: scores, gid, top-k masks ================================
// grid 64, block 576
__global__ void __launch_bounds__(576) k_post(const float* __restrict__ local,
                                              float* __restrict__ out) {
    __shared__ float sc[1024];
    __shared__ float sts[PP];
    __shared__ float sng[NG];
    __shared__ float red[1024];
    __shared__ float sms[2];
    __shared__ int scnt;
    __shared__ unsigned char smask[PP];
    int b = blockIdx.x, tid = threadIdx.x;

    if (tid < NG) red[tid] = g_gflow[b * NG + tid];
    __syncthreads();
    if (tid == 0) {
        float m = 0.f;
        for (int i = 0; i < NG; i++) m += red[i];
        m /= (float)NG;
        float v = 0.f;
        for (int i = 0; i < NG; i++) { float d = red[i] - m; v += d * d; }
        float sd = fmaxf(sqrtf(v / 63.f), 1e-6f);
        sms[0] = m; sms[1] = sd;
    }
    __syncthreads();
    if (tid < NG) sng[tid] = (red[tid] - sms[0]) / sms[1];
    __syncthreads();

    float lv = local[b * PP + tid];
    red[tid] = lv; if (tid < 448) red[PP + tid] = 0.f;
    __syncthreads();
    for (int st = 512; st >= 1; st >>= 1) {
        if (tid < st) red[tid] += red[tid + st];
        __syncthreads();
    }
    float lmean = red[0] / (float)PP;
    __syncthreads();
    float dlv = lv - lmean;
    red[tid] = dlv * dlv; if (tid < 448) red[PP + tid] = 0.f;
    __syncthreads();
    for (int st = 512; st >= 1; st >>= 1) {
        if (tid < st) red[tid] += red[tid + st];
        __syncthreads();
    }
    float lstd = fmaxf(sqrtf(red[0] / 575.f), 1e-6f);
    __syncthreads();
    float nloc = dlv / lstd;

    int gid = ((tid / 24) / 3) * 8 + ((tid % 24) / 3);
    float gs = sng[gid];
    float ts = gs + 0.5f * nloc;
    out[OFF_GID + b * PP + tid] = (float)gid;
    out[OFF_GS  + b * PP + tid] = gs;
    sts[tid] = ts;
    sc[tid] = ts; if (tid < 448) sc[PP + tid] = -3.4e38f;
    if (tid == 0) scnt = 0;
    __syncthreads();
    // bitonic ascending sort of 1024
    for (int k = 2; k <= 1024; k <<= 1)
        for (int j = k >> 1; j > 0; j >>= 1) {
            for (int i = tid; i < 1024; i += 576) {
                int ixj = i ^ j;
                if (ixj > i) {
                    float x = sc[i], y = sc[ixj];
                    if (((i & k) == 0) == (x > y)) { sc[i] = y; sc[ixj] = x; }
                }
            }
            __syncthreads();
        }
    float thr = sc[1024 - 288];   // 288th largest
    int m = (ts > thr) ? 1 : 0;
    if (m) atomicAdd(&scnt, 1);
    smask[tid] = (unsigned char)m;
    __syncthreads();
    if (tid == 0) {   // fill ties in ascending index order (matches lax.top_k)
        int rem = 288 - scnt;
        for (int t = 0; t < PP && rem > 0; t++)
            if (!smask[t] && sts[t] == thr) { smask[t] = 1; rem--; }
    }
    __syncthreads();
    float mv = smask[tid] ? 1.f : 0.f;
    out[OFF_PKEEP + b * PP + tid] = mv;
    out[OFF_KEEP + b * (PP + 1) + 1 + tid] = mv;
    if (tid == 0) out[OFF_KEEP + b * (PP + 1)] = 1.f;
}

// ============ K7: aux scalars =============================================
__global__ void k_aux(float* __restrict__ out) {
    if (threadIdx.x == 0) {
        float a = 0.f, c = 0.f;
        for (int i = 0; i < BB; i++) { a += g_auxsp[i]; c += g_auxst[i]; }
        out[OFF_AS]  = a / (float)BB;
        out[OFF_AST] = c / (float)BB;
    }
}

// ============ launcher ====================================================
extern "C" void kernel_launch(void* const* d_in, const int* in_sizes, int n_in,
                              void* d_out, int out_size) {
    (void)in_sizes; (void)n_in; (void)out_size;
    const float* tokens = (const float*)d_in[0];
    const float* cls    = (const float*)d_in[1];
    const float* Wm     = (const float*)d_in[2];
    const float* local  = (const float*)d_in[3];
    float* out = (float*)d_out;

    k_nodes<<<dim3(NN, BB), 192>>>(tokens, cls);
    k_gemm <<<dim3(65, 6), 256>>>(Wm);
    k_gram <<<dim3(BB, 3), 169>>>();
    k_c0   <<<BB, 256>>>(out);
    k_dyn  <<<BB, 416>>>(out);
    k_post <<<BB, 576>>>(local, out);
    k_aux  <<<1, 64>>>(out);
}

// round 2
// speedup vs baseline: 1.2245x; 1.2245x over previous
#include <cuda_runtime.h>
#include <math.h>

// ---------------- problem constants ----------------
#define BB 64
#define PP 576
#define DD 768
#define NG 64
#define NN 65
#define NSTEPS 8

// ---------------- output layout (float32, concatenated in tuple order) ----
#define OFF_KEEP  0          // B*(P+1) = 36928
#define OFF_PKEEP 36928      // B*P     = 36864
#define OFF_GID   73792      // B*P
#define OFF_GS    110656     // B*P
#define OFF_DH    147520     // B*9*65*65 = 2433600
#define OFF_QH    2581120    // B*8*65*65 = 2163200
#define OFF_RT    4744320    // B*64*64   = 262144
#define OFF_AS    5006464
#define OFF_AST   5006465

// ---------------- scratch (static device globals; no allocation) ----------
__device__ float g_nodes[BB * NN * DD];        // 12.2 MB
__device__ float g_proj [BB * NN * DD];        // 12.2 MB
__device__ float g_gramp[BB * 6 * NN * NN];    // K-split partials (6 slabs)
__device__ float g_gflow[BB * NG];
__device__ float g_auxsp[BB];
__device__ float g_auxst[BB];

// packed f32x2 FMA (FFMA2) — ptxas never emits this from C++; PTX only.
__device__ __forceinline__ void fma2(unsigned long long &acc, float a,
                                     unsigned long long b) {
    unsigned long long aa;
    asm("mov.b64 %0, {%1, %1};" : "=l"(aa) : "f"(a));
    asm("fma.rn.f32x2 %0, %1, %2, %0;" : "+l"(acc) : "l"(aa), "l"(b));
}

// ============ K1: group pooling -> nodes (B,65,768) =======================
// grid (65, B), block 192 (one float4 per thread)
__global__ void k_nodes(const float* __restrict__ tokens,
                        const float* __restrict__ cls) {
    int n = blockIdx.x, b = blockIdx.y, t = threadIdx.x;
    float4* dst = (float4*)&g_nodes[(b * NN + n) * DD];
    if (n == 0) {
        dst[t] = ((const float4*)&cls[b * DD])[t];
    } else {
        int g = n - 1, gr = g >> 3, gc = g & 7;
        float4 s = make_float4(0.f, 0.f, 0.f, 0.f);
#pragma unroll
        for (int rr = 0; rr < 3; rr++)
#pragma unroll
            for (int cc = 0; cc < 3; cc++) {
                int p = (gr * 3 + rr) * 24 + gc * 3 + cc;
                float4 v = ((const float4*)&tokens[(b * PP + p) * DD])[t];
                s.x += v.x; s.y += v.y; s.z += v.z; s.w += v.w;
            }
        const float inv9 = 1.f / 9.f;
        s.x *= inv9; s.y *= inv9; s.z *= inv9; s.w *= inv9;
        dst[t] = s;
    }
}

// ============ K2: proj = nodes(4160x768) @ W^T(768x768) ===================
// grid (65, 6), block 256; 64x128 tile, BK=16 double-buffered, 1 sync/slab
__global__ void __launch_bounds__(256) k_gemm(const float* __restrict__ Wm) {
    __shared__ __align__(16) float As[2][16][64];
    __shared__ __align__(8)  float Bs[2][16][130];
    int bm = blockIdx.x * 64, bn = blockIdx.y * 128;
    int tid = threadIdx.x;
    int tx = tid & 15, ty = tid >> 4;

    // per-slab loads: A = 256 float4 (1/thread); B = 512 float4 (2/thread)
    int ar = tid >> 2, ac = tid & 3;           // A: row 0..63, col-group 0..3
    int br0 = tid >> 2;                        // B rows 0..63 and 64..127
    const float* Ag  = &g_nodes[(bm + ar) * DD + ac * 4];
    const float* Bg0 = &Wm[(bn + br0) * DD + ac * 4];
    const float* Bg1 = &Wm[(bn + br0 + 64) * DD + ac * 4];

    float4 ra  = *(const float4*)(Ag);
    float4 rb0 = *(const float4*)(Bg0);
    float4 rb1 = *(const float4*)(Bg1);
    As[0][ac * 4 + 0][ar] = ra.x;  As[0][ac * 4 + 1][ar] = ra.y;
    As[0][ac * 4 + 2][ar] = ra.z;  As[0][ac * 4 + 3][ar] = ra.w;
    Bs[0][ac * 4 + 0][br0] = rb0.x; Bs[0][ac * 4 + 1][br0] = rb0.y;
    Bs[0][ac * 4 + 2][br0] = rb0.z; Bs[0][ac * 4 + 3][br0] = rb0.w;
    Bs[0][ac * 4 + 0][br0 + 64] = rb1.x; Bs[0][ac * 4 + 1][br0 + 64] = rb1.y;
    Bs[0][ac * 4 + 2][br0 + 64] = rb1.z; Bs[0][ac * 4 + 3][br0 + 64] = rb1.w;
    __syncthreads();

    unsigned long long acc[4][4];
#pragma unroll
    for (int i = 0; i < 4; i++)
#pragma unroll
        for (int j = 0; j < 4; j++) acc[i][j] = 0ull;

    const int NSLAB = DD / 16;   // 48
    for (int s = 0; s < NSLAB; s++) {
        int cur = s & 1;
        if (s < NSLAB - 1) {
            int k0 = (s + 1) * 16;
            ra  = *(const float4*)(Ag  + k0);
            rb0 = *(const float4*)(Bg0 + k0);
            rb1 = *(const float4*)(Bg1 + k0);
        }
#pragma unroll
        for (int kk = 0; kk < 16; kk++) {
            float4 a = *(const float4*)&As[cur][kk][ty * 4];
            unsigned long long b0 = *(const unsigned long long*)&Bs[cur][kk][tx * 2 + 0];
            unsigned long long b1 = *(const unsigned long long*)&Bs[cur][kk][tx * 2 + 32];
            unsigned long long b2 = *(const unsigned long long*)&Bs[cur][kk][tx * 2 + 64];
            unsigned long long b3 = *(const unsigned long long*)&Bs[cur][kk][tx * 2 + 96];
            fma2(acc[0][0], a.x, b0); fma2(acc[0][1], a.x, b1);
            fma2(acc[0][2], a.x, b2); fma2(acc[0][3], a.x, b3);
            fma2(acc[1][0], a.y, b0); fma2(acc[1][1], a.y, b1);
            fma2(acc[1][2], a.y, b2); fma2(acc[1][3], a.y, b3);
            fma2(acc[2][0], a.z, b0); fma2(acc[2][1], a.z, b1);
            fma2(acc[2][2], a.z, b2); fma2(acc[2][3], a.z, b3);
            fma2(acc[3][0], a.w, b0); fma2(acc[3][1], a.w, b1);
            fma2(acc[3][2], a.w, b2); fma2(acc[3][3], a.w, b3);
        }
        if (s < NSLAB - 1) {
            int nxt = cur ^ 1;
            As[nxt][ac * 4 + 0][ar] = ra.x;  As[nxt][ac * 4 + 1][ar] = ra.y;
            As[nxt][ac * 4 + 2][ar] = ra.z;  As[nxt][ac * 4 + 3][ar] = ra.w;
            Bs[nxt][ac * 4 + 0][br0] = rb0.x; Bs[nxt][ac * 4 + 1][br0] = rb0.y;
            Bs[nxt][ac * 4 + 2][br0] = rb0.z; Bs[nxt][ac * 4 + 3][br0] = rb0.w;
            Bs[nxt][ac * 4 + 0][br0 + 64] = rb1.x; Bs[nxt][ac * 4 + 1][br0 + 64] = rb1.y;
            Bs[nxt][ac * 4 + 2][br0 + 64] = rb1.z; Bs[nxt][ac * 4 + 3][br0 + 64] = rb1.w;
        }
        __syncthreads();
    }
#pragma unroll
    for (int i = 0; i < 4; i++) {
        int m = bm + ty * 4 + i;
#pragma unroll
        for (int j = 0; j < 4; j++) {
            int n = bn + tx * 2 + j * 32;
            *(unsigned long long*)&g_proj[m * DD + n] = acc[i][j];
        }
    }
}

// ============ K3: Gram partials G = proj proj^T, K-split 6 ================
// grid (B, 6), block 169 (13x13 threads, 5x5 outputs each)
__global__ void k_gram() {
    __shared__ float S[64][65];
    int b = blockIdx.x, ks = blockIdx.y;
    int tid = threadIdx.x;
    int tx = tid % 13, ty = tid / 13;
    float acc[5][5];
#pragma unroll
    for (int i = 0; i < 5; i++)
#pragma unroll
        for (int j = 0; j < 5; j++) acc[i][j] = 0.f;

    for (int sub = 0; sub < 2; sub++) {
        int kb = ks * 128 + sub * 64;
        __syncthreads();
        for (int t = tid; t < 1040; t += 169) {
            int n = t / 16, c = t % 16;
            float4 v = *(const float4*)&g_proj[(b * NN + n) * DD + kb + c * 4];
            S[c * 4 + 0][n] = v.x; S[c * 4 + 1][n] = v.y;
            S[c * 4 + 2][n] = v.z; S[c * 4 + 3][n] = v.w;
        }
        __syncthreads();
        for (int kk = 0; kk < 64; kk++) {
            float av[5], bv[5];
#pragma unroll
            for (int i = 0; i < 5; i++) { av[i] = S[kk][ty * 5 + i]; bv[i] = S[kk][tx * 5 + i]; }
#pragma unroll
            for (int i = 0; i < 5; i++)
#pragma unroll
                for (int j = 0; j < 5; j++) acc[i][j] += av[i] * bv[j];
        }
    }
    float* gp = &g_gramp[(size_t)(b * 6 + ks) * (NN * NN)];
#pragma unroll
    for (int i = 0; i < 5; i++)
#pragma unroll
        for (int j = 0; j < 5; j++)
            gp[(ty * 5 + i) * NN + (tx * 5 + j)] = acc[i][j];
}

// ============ K4: C0 + dynamics — register-resident Gauss-Jordan ==========
// grid 64, block 416. One barrier per pivot via parity-double-buffered
// pivot-row / pivot-column staging.
__global__ void __launch_bounds__(416) k_dyn(float* __restrict__ out) {
    __shared__ float sC[NN * 66];          // C matrix, stride 66
    __shared__ float spiv[2][68];          // pivot row staging (parity)
    __shared__ float sfb[2][NN];           // column-k staging (parity)
    __shared__ float sdeg[NN];
    __shared__ float sp[NN];
    __shared__ float spart[NN * 6];        // deg partials
    __shared__ float sdiag[NN], srhs[NN];
    __shared__ float sinv[NN];
    __shared__ float sred[512];

    int b = blockIdx.x, tid = threadIdx.x;
    int row = tid / 6, ch = tid - row * 6, c0 = ch * 11;
    bool act = (tid < 390);
    const float* gp = &g_gramp[(size_t)b * 6 * NN * NN];
    float* dh = out + OFF_DH + (size_t)b * 9 * NN * NN;
    float* qh = out + OFF_QH + (size_t)b * 8 * NN * NN;

    // ---- C0 = floor(exp(-(2 - 2 cos))) ----
    if (tid < NN) {
        int d = tid * NN + tid;
        float g = 0.f;
#pragma unroll
        for (int s = 0; s < 6; s++) g += gp[s * NN * NN + d];
        sinv[tid] = rsqrtf(g);
    }
    __syncthreads();
    for (int idx = tid; idx < NN * NN; idx += 416) {
        int i = idx / NN, j = idx - i * NN;
        float c = 0.f;
        if (i != j) {
            float g = 0.f;
#pragma unroll
            for (int s = 0; s < 6; s++) g += gp[s * NN * NN + idx];
            float dot = g * sinv[i] * sinv[j];
            float d2 = fmaxf(2.f - 2.f * dot, 0.f);
            c = fmaxf(__expf(-d2), 1e-4f);
        }
        sC[i * 66 + j] = c;
        dh[idx] = c;
    }
    float auxst = 0.f;

    for (int s = 0; s < NSTEPS; s++) {
        __syncthreads();
        // ---- degrees (chunked partials) ----
        if (act) {
            float p = 0.f;
            int cend = c0 + 11; if (cend > NN) cend = NN;
            for (int c = c0; c < cend; c++) p += sC[row * 66 + c];
            spart[row * 6 + ch] = p;
        }
        __syncthreads();
        if (tid < NN) {
            float d = 0.f;
#pragma unroll
            for (int q = 0; q < 6; q++) d += spart[tid * 6 + q];
            sdeg[tid] = d;
        }
        __syncthreads();
        // ---- build A rows in registers; publish pivot 0 ----
        float a[11];
        if (act) {
#pragma unroll
            for (int j = 0; j < 11; j++) {
                int c = c0 + j;
                float v;
                if (c == 65)      v = (row == 0) ? 1.f : (-1.f / 64.f);
                else if (c == row) v = sdeg[row] + 1e-4f;
                else               v = -sC[row * 66 + c];
                a[j] = v;
            }
            if (ch == 0) sfb[0][row] = a[0];
            if (row == 0) {
#pragma unroll
                for (int j = 0; j < 11; j++) spiv[0][c0 + j] = a[j];
            }
        }
        __syncthreads();
        // ---- Gauss-Jordan: one barrier per pivot ----
        for (int k = 0; k < NN; k++) {
            int pb = k & 1;
            if (act && row != k) {
                float f = __fdividef(sfb[pb][row], spiv[pb][k]);
#pragma unroll
                for (int j = 0; j < 11; j++)
                    if (c0 + j > k) a[j] -= f * spiv[pb][c0 + j];
            }
            if (act && k < NN - 1) {
                int kn = k + 1, nb = kn & 1;
                if (c0 <= kn && kn < c0 + 11) sfb[nb][row] = a[kn - c0];
                if (row == kn) {
#pragma unroll
                    for (int j = 0; j < 11; j++) spiv[nb][c0 + j] = a[j];
                }
            }
            __syncthreads();
        }
        // ---- extract p ----
        if (act) {
            if (ch == 5) srhs[row] = a[10];
            if (c0 <= row && row < c0 + 11) sdiag[row] = a[row - c0];
        }
        __syncthreads();
        if (tid < NN) sp[tid] = __fdividef(srhs[tid], sdiag[tid]);
        __syncthreads();
        // ---- group flow from LAST step (pre-update C) ----
        if (s == NSTEPS - 1 && tid < NG) {
            int i = tid + 1;
            float accf = 0.f, pi = sp[i];
            for (int j = 0; j < NN; j++) accf += fabsf(sC[i * 66 + j] * (pi - sp[j]));
            g_gflow[b * NG + tid] = accf;
        }
        __syncthreads();
        // ---- flow, history, C update ----
        float* dhs = dh + (size_t)(s + 1) * NN * NN;
        float* qhs = qh + (size_t)s * NN * NN;
        for (int idx = tid; idx < NN * NN; idx += 416) {
            int i = idx / NN, j = idx - i * NN;
            float c = sC[i * 66 + j];
            float fl = c * (sp[i] - sp[j]);
            qhs[idx] = fl;
            float aab = fabsf(fl);
            float r = aab / (1.f + aab);
            float cn = c + 0.1f * (r - 0.1f * c);
            cn = fmaxf(cn, 0.f);
            cn = (i == j) ? 0.f : fmaxf(cn, 1e-4f);
            auxst += fabsf(cn - c);
            sC[i * 66 + j] = cn;
            dhs[idx] = cn;
        }
    }
    __syncthreads();
    // ---- aux_sparse ----
    float asp = 0.f;
    for (int idx = tid; idx < NN * NN; idx += 416) {
        int i = idx / NN, j = idx - i * NN;
        if (i >= 1 && j >= 1) asp += sC[i * 66 + j];
    }
    sred[tid] = asp; __syncthreads();
    for (int st = 256; st >= 1; st >>= 1) {
        if (tid < st && tid + st < 416) sred[tid] += sred[tid + st];
        __syncthreads();
    }
    if (tid == 0) g_auxsp[b] = sred[0];
    __syncthreads();
    sred[tid] = auxst; __syncthreads();
    for (int st = 256; st >= 1; st >>= 1) {
        if (tid < st && tid + st < 416) sred[tid] += sred[tid + st];
        __syncthreads();
    }
    if (tid == 0) g_auxst[b] = sred[0];
    __syncthreads();
    // ---- routing ----
    if (tid < NG) {
        int i = tid + 1;
        float rs = 0.f;
        for (int j = 1; j < NN; j++) rs += sC[i * 66 + j];
        srhs[tid] = fmaxf(rs, 1e-6f);
    }
    __syncthreads();
    float* rt = out + OFF_RT + (size_t)b * NG * NG;
    for (int idx = tid; idx < NG * NG; idx += 416) {
        int i = idx / NG, j = idx - i * NG;
        rt[idx] = __fdividef(sC[(i + 1) * 66 + (j + 1)], srhs[i]);
    }
}

// ============ K5: scores, gid, top-k masks (+aux scalars in block 0) ======
// grid 64, block 576
__global__ void __launch_bounds__(576) k_post(const float* __restrict__ local,
                                              float* __restrict__ out) {
    __shared__ float sc[1024];
    __shared__ float sts[PP];
    __shared__ float sng[NG];
    __shared__ float red[1024];
    __shared__ float sms[2];
    __shared__ int scnt;
    __shared__ unsigned char smask[PP];
    int b = blockIdx.x, tid = threadIdx.x;

    // aux scalars (block 0, warp 0 — no barriers in this path)
    if (b == 0 && tid < 32) {
        float v1 = g_auxsp[tid] + g_auxsp[tid + 32];
        float v2 = g_auxst[tid] + g_auxst[tid + 32];
#pragma unroll
        for (int off = 16; off >= 1; off >>= 1) {
            v1 += __shfl_down_sync(0xffffffffu, v1, off);
            v2 += __shfl_down_sync(0xffffffffu, v2, off);
        }
        if (tid == 0) { out[OFF_AS] = v1 / (float)BB; out[OFF_AST] = v2 / (float)BB; }
    }

    if (tid < NG) red[tid] = g_gflow[b * NG + tid];
    __syncthreads();
    if (tid == 0) {
        float m = 0.f;
        for (int i = 0; i < NG; i++) m += red[i];
        m /= (float)NG;
        float v = 0.f;
        for (int i = 0; i < NG; i++) { float d = red[i] - m; v += d * d; }
        float sd = fmaxf(sqrtf(v / 63.f), 1e-6f);
        sms[0] = m; sms[1] = sd;
    }
    __syncthreads();
    if (tid < NG) sng[tid] = (red[tid] - sms[0]) / sms[1];
    __syncthreads();

    float lv = local[b * PP + tid];
    red[tid] = lv; if (tid < 448) red[PP + tid] = 0.f;
    __syncthreads();
    for (int st = 512; st >= 1; st >>= 1) {
        if (tid < st) red[tid] += red[tid + st];
        __syncthreads();
    }
    float lmean = red[0] / (float)PP;
    __syncthreads();
    float dlv = lv - lmean;
    red[tid] = dlv * dlv; if (tid < 448) red[PP + tid] = 0.f;
    __syncthreads();
    for (int st = 512; st >= 1; st >>= 1) {
        if (tid < st) red[tid] += red[tid + st];
        __syncthreads();
    }
    float lstd = fmaxf(sqrtf(red[0] / 575.f), 1e-6f);
    __syncthreads();
    float nloc = dlv / lstd;

    int gid = ((tid / 24) / 3) * 8 + ((tid % 24) / 3);
    float gs = sng[gid];
    float ts = gs + 0.5f * nloc;
    out[OFF_GID + b * PP + tid] = (float)gid;
    out[OFF_GS  + b * PP + tid] = gs;
    sts[tid] = ts;
    sc[tid] = ts; if (tid < 448) sc[PP + tid] = -3.4e38f;
    if (tid == 0) scnt = 0;
    __syncthreads();
    // bitonic ascending sort of 1024
    for (int k = 2; k <= 1024; k <<= 1)
        for (int j = k >> 1; j > 0; j >>= 1) {
            for (int i = tid; i < 1024; i += 576) {
                int ixj = i ^ j;
                if (ixj > i) {
                    float x = sc[i], y = sc[ixj];
                    if (((i & k) == 0) == (x > y)) { sc[i] = y; sc[ixj] = x; }
                }
            }
            __syncthreads();
        }
    float thr = sc[1024 - 288];   // 288th largest
    int m = (ts > thr) ? 1 : 0;
    if (m) atomicAdd(&scnt, 1);
    smask[tid] = (unsigned char)m;
    __syncthreads();
    if (tid == 0) {   // fill ties in ascending index order (matches lax.top_k)
        int rem = 288 - scnt;
        for (int t = 0; t < PP && rem > 0; t++)
            if (!smask[t] && sts[t] == thr) { smask[t] = 1; rem--; }
    }
    __syncthreads();
    float mv = smask[tid] ? 1.f : 0.f;
    out[OFF_PKEEP + b * PP + tid] = mv;
    out[OFF_KEEP + b * (PP + 1) + 1 + tid] = mv;
    if (tid == 0) out[OFF_KEEP + b * (PP + 1)] = 1.f;
}

// ============ launcher ====================================================
extern "C" void kernel_launch(void* const* d_in, const int* in_sizes, int n_in,
                              void* d_out, int out_size) {
    (void)in_sizes; (void)n_in; (void)out_size;
    const float* tokens = (const float*)d_in[0];
    const float* cls    = (const float*)d_in[1];
    const float* Wm     = (const float*)d_in[2];
    const float* local  = (const float*)d_in[3];
    float* out = (float*)d_out;

    k_nodes<<<dim3(NN, BB), 192>>>(tokens, cls);
    k_gemm <<<dim3(65, 6), 256>>>(Wm);
    k_gram <<<dim3(BB, 6), 169>>>();
    k_dyn  <<<BB, 416>>>(out);
    k_post <<<BB, 576>>>(local, out);
}

// round 3
// speedup vs baseline: 1.5157x; 1.2378x over previous
#include <cuda_runtime.h>
#include <math.h>

// ---------------- problem constants ----------------
#define BB 64
#define PP 576
#define DD 768
#define NG 64
#define NN 65
#define NSTEPS 8
#define SW 72              // padded matrix stride (6 chunks x 12)

// ---------------- output layout (float32, concatenated in tuple order) ----
#define OFF_KEEP  0          // B*(P+1) = 36928
#define OFF_PKEEP 36928      // B*P     = 36864
#define OFF_GID   73792      // B*P
#define OFF_GS    110656     // B*P
#define OFF_DH    147520     // B*9*65*65 = 2433600
#define OFF_QH    2581120    // B*8*65*65 = 2163200
#define OFF_RT    4744320    // B*64*64   = 262144
#define OFF_AS    5006464
#define OFF_AST   5006465

// ---------------- scratch (static device globals; no allocation) ----------
__device__ float g_nodes[BB * NN * DD];        // 12.2 MB
__device__ float g_proj [BB * NN * DD];        // 12.2 MB
__device__ float g_gramp[BB * 6 * NN * NN];    // K-split partials (6 slabs)
__device__ float g_gflow[BB * NG];
__device__ float g_auxsp[BB];
__device__ float g_auxst[BB];

// packed f32x2 FMA (FFMA2) — ptxas never emits this from C++; PTX only.
__device__ __forceinline__ void fma2(unsigned long long &acc, float a,
                                     unsigned long long b) {
    unsigned long long aa;
    asm("mov.b64 %0, {%1, %1};" : "=l"(aa) : "f"(a));
    asm("fma.rn.f32x2 %0, %1, %2, %0;" : "+l"(acc) : "l"(aa), "l"(b));
}

// ============ K1: group pooling -> nodes (B,65,768) =======================
__global__ void k_nodes(const float* __restrict__ tokens,
                        const float* __restrict__ cls) {
    int n = blockIdx.x, b = blockIdx.y, t = threadIdx.x;
    float4* dst = (float4*)&g_nodes[(b * NN + n) * DD];
    if (n == 0) {
        dst[t] = ((const float4*)&cls[b * DD])[t];
    } else {
        int g = n - 1, gr = g >> 3, gc = g & 7;
        float4 s = make_float4(0.f, 0.f, 0.f, 0.f);
#pragma unroll
        for (int rr = 0; rr < 3; rr++)
#pragma unroll
            for (int cc = 0; cc < 3; cc++) {
                int p = (gr * 3 + rr) * 24 + gc * 3 + cc;
                float4 v = ((const float4*)&tokens[(b * PP + p) * DD])[t];
                s.x += v.x; s.y += v.y; s.z += v.z; s.w += v.w;
            }
        const float inv9 = 1.f / 9.f;
        s.x *= inv9; s.y *= inv9; s.z *= inv9; s.w *= inv9;
        dst[t] = s;
    }
}

// ============ K2: proj = nodes(4160x768) @ W^T(768x768) ===================
__global__ void __launch_bounds__(256) k_gemm(const float* __restrict__ Wm) {
    __shared__ __align__(16) float As[2][16][64];
    __shared__ __align__(8)  float Bs[2][16][130];
    int bm = blockIdx.x * 64, bn = blockIdx.y * 128;
    int tid = threadIdx.x;
    int tx = tid & 15, ty = tid >> 4;

    int ar = tid >> 2, ac = tid & 3;
    int br0 = tid >> 2;
    const float* Ag  = &g_nodes[(bm + ar) * DD + ac * 4];
    const float* Bg0 = &Wm[(bn + br0) * DD + ac * 4];
    const float* Bg1 = &Wm[(bn + br0 + 64) * DD + ac * 4];

    float4 ra  = *(const float4*)(Ag);
    float4 rb0 = *(const float4*)(Bg0);
    float4 rb1 = *(const float4*)(Bg1);
    As[0][ac * 4 + 0][ar] = ra.x;  As[0][ac * 4 + 1][ar] = ra.y;
    As[0][ac * 4 + 2][ar] = ra.z;  As[0][ac * 4 + 3][ar] = ra.w;
    Bs[0][ac * 4 + 0][br0] = rb0.x; Bs[0][ac * 4 + 1][br0] = rb0.y;
    Bs[0][ac * 4 + 2][br0] = rb0.z; Bs[0][ac * 4 + 3][br0] = rb0.w;
    Bs[0][ac * 4 + 0][br0 + 64] = rb1.x; Bs[0][ac * 4 + 1][br0 + 64] = rb1.y;
    Bs[0][ac * 4 + 2][br0 + 64] = rb1.z; Bs[0][ac * 4 + 3][br0 + 64] = rb1.w;
    __syncthreads();

    unsigned long long acc[4][4];
#pragma unroll
    for (int i = 0; i < 4; i++)
#pragma unroll
        for (int j = 0; j < 4; j++) acc[i][j] = 0ull;

    const int NSLAB = DD / 16;   // 48
    for (int s = 0; s < NSLAB; s++) {
        int cur = s & 1;
        if (s < NSLAB - 1) {
            int k0 = (s + 1) * 16;
            ra  = *(const float4*)(Ag  + k0);
            rb0 = *(const float4*)(Bg0 + k0);
            rb1 = *(const float4*)(Bg1 + k0);
        }
#pragma unroll
        for (int kk = 0; kk < 16; kk++) {
            float4 a = *(const float4*)&As[cur][kk][ty * 4];
            unsigned long long b0 = *(const unsigned long long*)&Bs[cur][kk][tx * 2 + 0];
            unsigned long long b1 = *(const unsigned long long*)&Bs[cur][kk][tx * 2 + 32];
            unsigned long long b2 = *(const unsigned long long*)&Bs[cur][kk][tx * 2 + 64];
            unsigned long long b3 = *(const unsigned long long*)&Bs[cur][kk][tx * 2 + 96];
            fma2(acc[0][0], a.x, b0); fma2(acc[0][1], a.x, b1);
            fma2(acc[0][2], a.x, b2); fma2(acc[0][3], a.x, b3);
            fma2(acc[1][0], a.y, b0); fma2(acc[1][1], a.y, b1);
            fma2(acc[1][2], a.y, b2); fma2(acc[1][3], a.y, b3);
            fma2(acc[2][0], a.z, b0); fma2(acc[2][1], a.z, b1);
            fma2(acc[2][2], a.z, b2); fma2(acc[2][3], a.z, b3);
            fma2(acc[3][0], a.w, b0); fma2(acc[3][1], a.w, b1);
            fma2(acc[3][2], a.w, b2); fma2(acc[3][3], a.w, b3);
        }
        if (s < NSLAB - 1) {
            int nxt = cur ^ 1;
            As[nxt][ac * 4 + 0][ar] = ra.x;  As[nxt][ac * 4 + 1][ar] = ra.y;
            As[nxt][ac * 4 + 2][ar] = ra.z;  As[nxt][ac * 4 + 3][ar] = ra.w;
            Bs[nxt][ac * 4 + 0][br0] = rb0.x; Bs[nxt][ac * 4 + 1][br0] = rb0.y;
            Bs[nxt][ac * 4 + 2][br0] = rb0.z; Bs[nxt][ac * 4 + 3][br0] = rb0.w;
            Bs[nxt][ac * 4 + 0][br0 + 64] = rb1.x; Bs[nxt][ac * 4 + 1][br0 + 64] = rb1.y;
            Bs[nxt][ac * 4 + 2][br0 + 64] = rb1.z; Bs[nxt][ac * 4 + 3][br0 + 64] = rb1.w;
        }
        __syncthreads();
    }
#pragma unroll
    for (int i = 0; i < 4; i++) {
        int m = bm + ty * 4 + i;
#pragma unroll
        for (int j = 0; j < 4; j++) {
            int n = bn + tx * 2 + j * 32;
            *(unsigned long long*)&g_proj[m * DD + n] = acc[i][j];
        }
    }
}

// ============ K3: Gram partials G = proj proj^T, K-split 6 ================
__global__ void k_gram() {
    __shared__ float S[64][65];
    int b = blockIdx.x, ks = blockIdx.y;
    int tid = threadIdx.x;
    int tx = tid % 13, ty = tid / 13;
    float acc[5][5];
#pragma unroll
    for (int i = 0; i < 5; i++)
#pragma unroll
        for (int j = 0; j < 5; j++) acc[i][j] = 0.f;

    for (int sub = 0; sub < 2; sub++) {
        int kb = ks * 128 + sub * 64;
        __syncthreads();
        for (int t = tid; t < 1040; t += 169) {
            int n = t / 16, c = t % 16;
            float4 v = *(const float4*)&g_proj[(b * NN + n) * DD + kb + c * 4];
            S[c * 4 + 0][n] = v.x; S[c * 4 + 1][n] = v.y;
            S[c * 4 + 2][n] = v.z; S[c * 4 + 3][n] = v.w;
        }
        __syncthreads();
        for (int kk = 0; kk < 64; kk++) {
            float av[5], bv[5];
#pragma unroll
            for (int i = 0; i < 5; i++) { av[i] = S[kk][ty * 5 + i]; bv[i] = S[kk][tx * 5 + i]; }
#pragma unroll
            for (int i = 0; i < 5; i++)
#pragma unroll
                for (int j = 0; j < 5; j++) acc[i][j] += av[i] * bv[j];
        }
    }
    float* gp = &g_gramp[(size_t)(b * 6 + ks) * (NN * NN)];
#pragma unroll
    for (int i = 0; i < 5; i++)
#pragma unroll
        for (int j = 0; j < 5; j++)
            gp[(ty * 5 + i) * NN + (tx * 5 + j)] = acc[i][j];
}

// ============ K4: C0 + dynamics — spill-free register Gauss-Jordan ========
// grid 64, block 416. One barrier per pivot; 12-wide chunks, all register
// indices static; f-multiplier via double-buffered sfball staging.
__global__ void __launch_bounds__(416) k_dyn(float* __restrict__ out) {
    __shared__ __align__(16) float sC[NN * SW];       // C, stride 72 (cols>=65 zero)
    __shared__ __align__(16) float spiv[2][SW + 4];   // pivot row staging
    __shared__ __align__(16) float sfball[2][NN][12]; // owner-chunk staging
    __shared__ float sdeg[NN];
    __shared__ float sp[NN];
    __shared__ float spart[NN * 6];
    __shared__ float sdiag[NN], srhs[NN];
    __shared__ float sinv[NN];
    __shared__ float sred[512];

    int b = blockIdx.x, tid = threadIdx.x;
    int row = tid / 6, ch = tid - row * 6, c0 = ch * 12;
    bool act = (tid < 390);
    const float* gp = &g_gramp[(size_t)b * 6 * NN * NN];
    float* dh = out + OFF_DH + (size_t)b * 9 * NN * NN;
    float* qh = out + OFF_QH + (size_t)b * 8 * NN * NN;

    // ---- zero padded C ----
    for (int idx = tid; idx < NN * SW; idx += 416) sC[idx] = 0.f;
    // ---- C0 = floor(exp(-(2 - 2 cos))) ----
    if (tid < NN) {
        int d = tid * NN + tid;
        float g = 0.f;
#pragma unroll
        for (int s = 0; s < 6; s++) g += gp[s * NN * NN + d];
        sinv[tid] = rsqrtf(g);
    }
    __syncthreads();
    {
        int i = tid / NN, j = tid - i * NN;
        for (int idx = tid; idx < NN * NN; idx += 416) {
            float c = 0.f;
            if (i != j) {
                float g = 0.f;
#pragma unroll
                for (int s = 0; s < 6; s++) g += gp[s * NN * NN + idx];
                float dot = g * sinv[i] * sinv[j];
                float d2 = fmaxf(2.f - 2.f * dot, 0.f);
                c = fmaxf(__expf(-d2), 1e-4f);
            }
            sC[i * SW + j] = c;
            dh[idx] = c;
            j += 26; i += 6; if (j >= NN) { j -= NN; i++; }   // +=416
        }
    }
    float auxst = 0.f;

    for (int s = 0; s < NSTEPS; s++) {
        __syncthreads();
        // ---- degrees: vectorized chunk partials ----
        if (act) {
            const float4* cr = (const float4*)&sC[row * SW + c0];
            float4 v0 = cr[0], v1 = cr[1], v2 = cr[2];
            spart[row * 6 + ch] = ((v0.x + v0.y) + (v0.z + v0.w))
                                + ((v1.x + v1.y) + (v1.z + v1.w))
                                + ((v2.x + v2.y) + (v2.z + v2.w));
        }
        __syncthreads();
        if (tid < NN) {
            float d = 0.f;
#pragma unroll
            for (int q = 0; q < 6; q++) d += spart[tid * 6 + q];
            sdeg[tid] = d;
        }
        __syncthreads();
        // ---- build A rows in registers; publish pivot-0 staging ----
        float a[12];
        if (act) {
            const float4* cr = (const float4*)&sC[row * SW + c0];
            float4 v0 = cr[0], v1 = cr[1], v2 = cr[2];
            a[0] = -v0.x; a[1] = -v0.y; a[2]  = -v0.z; a[3]  = -v0.w;
            a[4] = -v1.x; a[5] = -v1.y; a[6]  = -v1.z; a[7]  = -v1.w;
            a[8] = -v2.x; a[9] = -v2.y; a[10] = -v2.z; a[11] = -v2.w;
            if (ch == 5) a[5] = (row == 0) ? 1.f : (-1.f / 64.f);   // col 65 = rhs
            float dg = sdeg[row] + 1e-4f;
#pragma unroll
            for (int j = 0; j < 12; j++) if (c0 + j == row) a[j] = dg;
            if (ch == 0) {           // stage pivot-0 multiplier column chunk
                float4* fb = (float4*)&sfball[0][row][0];
                fb[0] = make_float4(a[0], a[1], a[2], a[3]);
                fb[1] = make_float4(a[4], a[5], a[6], a[7]);
                fb[2] = make_float4(a[8], a[9], a[10], a[11]);
            }
            if (row == 0) {
                float4* pv = (float4*)&spiv[0][c0];
                pv[0] = make_float4(a[0], a[1], a[2], a[3]);
                pv[1] = make_float4(a[4], a[5], a[6], a[7]);
                pv[2] = make_float4(a[8], a[9], a[10], a[11]);
            }
        }
        __syncthreads();
        // ---- Gauss-Jordan: one barrier per pivot, all-static reg indices ----
        int jk = 0, chk = 0;        // pivot k's column-in-chunk and owner chunk
        for (int k = 0; k < NN; k++) {
            int pb = k & 1, nb = pb ^ 1;
            if (act) {
                float piv  = spiv[pb][k];
                float fsrc = sfball[pb][row][jk];
                float f = __fdividef(fsrc, piv);
                f = (row == k) ? 0.f : f;
                const float4* pv = (const float4*)&spiv[pb][c0];
                float4 p0 = pv[0], p1 = pv[1], p2 = pv[2];
                a[0] -= f * p0.x; a[1] -= f * p0.y; a[2]  -= f * p0.z; a[3]  -= f * p0.w;
                a[4] -= f * p1.x; a[5] -= f * p1.y; a[6]  -= f * p1.z; a[7]  -= f * p1.w;
                a[8] -= f * p2.x; a[9] -= f * p2.y; a[10] -= f * p2.z; a[11] -= f * p2.w;
                if (k < NN - 1) {
                    int chn = (jk == 11) ? chk + 1 : chk;    // owner of col k+1
                    if (ch == chn) {
                        float4* fb = (float4*)&sfball[nb][row][0];
                        fb[0] = make_float4(a[0], a[1], a[2], a[3]);
                        fb[1] = make_float4(a[4], a[5], a[6], a[7]);
                        fb[2] = make_float4(a[8], a[9], a[10], a[11]);
                    }
                    if (row == k + 1) {
                        float4* pv2 = (float4*)&spiv[nb][c0];
                        pv2[0] = make_float4(a[0], a[1], a[2], a[3]);
                        pv2[1] = make_float4(a[4], a[5], a[6], a[7]);
                        pv2[2] = make_float4(a[8], a[9], a[10], a[11]);
                    }
                }
            }
            __syncthreads();
            jk++; if (jk == 12) { jk = 0; chk++; }
        }
        // ---- extract p = rhs / diag (all static indices) ----
        if (act) {
            if (ch == 5) srhs[row] = a[5];                  // col 65
#pragma unroll
            for (int j = 0; j < 12; j++) if (c0 + j == row) sdiag[row] = a[j];
        }
        __syncthreads();
        if (tid < NN) sp[tid] = __fdividef(srhs[tid], sdiag[tid]);
        __syncthreads();
        // ---- group flow from LAST step (pre-update C) ----
        if (s == NSTEPS - 1 && tid < NG) {
            int i = tid + 1;
            float accf = 0.f, pi = sp[i];
            for (int j = 0; j < NN; j++) accf += fabsf(sC[i * SW + j] * (pi - sp[j]));
            g_gflow[b * NG + tid] = accf;
        }
        __syncthreads();
        // ---- flow, history, C update ----
        float* dhs = dh + (size_t)(s + 1) * NN * NN;
        float* qhs = qh + (size_t)s * NN * NN;
        {
            int i = tid / NN, j = tid - i * NN;
            for (int idx = tid; idx < NN * NN; idx += 416) {
                float c = sC[i * SW + j];
                float fl = c * (sp[i] - sp[j]);
                qhs[idx] = fl;
                float aab = fabsf(fl);
                float r = aab / (1.f + aab);
                float cn = c + 0.1f * (r - 0.1f * c);
                cn = fmaxf(cn, 0.f);
                cn = (i == j) ? 0.f : fmaxf(cn, 1e-4f);
                auxst += fabsf(cn - c);
                sC[i * SW + j] = cn;
                dhs[idx] = cn;
                j += 26; i += 6; if (j >= NN) { j -= NN; i++; }
            }
        }
    }
    __syncthreads();
    // ---- aux_sparse ----
    float asp = 0.f;
    {
        int i = tid / NN, j = tid - i * NN;
        for (int idx = tid; idx < NN * NN; idx += 416) {
            if (i >= 1 && j >= 1) asp += sC[i * SW + j];
            j += 26; i += 6; if (j >= NN) { j -= NN; i++; }
        }
    }
    sred[tid] = asp; __syncthreads();
    for (int st = 256; st >= 1; st >>= 1) {
        if (tid < st && tid + st < 416) sred[tid] += sred[tid + st];
        __syncthreads();
    }
    if (tid == 0) g_auxsp[b] = sred[0];
    __syncthreads();
    sred[tid] = auxst; __syncthreads();
    for (int st = 256; st >= 1; st >>= 1) {
        if (tid < st && tid + st < 416) sred[tid] += sred[tid + st];
        __syncthreads();
    }
    if (tid == 0) g_auxst[b] = sred[0];
    __syncthreads();
    // ---- routing ----
    if (tid < NG) {
        int i = tid + 1;
        float rs = 0.f;
        for (int j = 1; j < NN; j++) rs += sC[i * SW + j];
        srhs[tid] = fmaxf(rs, 1e-6f);
    }
    __syncthreads();
    float* rt = out + OFF_RT + (size_t)b * NG * NG;
    {
        int i = tid / NG, j = tid - i * NG;
        for (int idx = tid; idx < NG * NG; idx += 416) {
            rt[idx] = __fdividef(sC[(i + 1) * SW + (j + 1)], srhs[i]);
            j += 32; i += 6; if (j >= NG) { j -= NG; i++; }
        }
    }
}

// ============ K5: scores, gid, top-k masks (+aux scalars in block 0) ======
__global__ void __launch_bounds__(576) k_post(const float* __restrict__ local,
                                              float* __restrict__ out) {
    __shared__ float sc[1024];
    __shared__ float sts[PP];
    __shared__ float sng[NG];
    __shared__ float red[1024];
    __shared__ float sms[2];
    __shared__ int scnt;
    __shared__ unsigned char smask[PP];
    int b = blockIdx.x, tid = threadIdx.x;

    if (b == 0 && tid < 32) {
        float v1 = g_auxsp[tid] + g_auxsp[tid + 32];
        float v2 = g_auxst[tid] + g_auxst[tid + 32];
#pragma unroll
        for (int off = 16; off >= 1; off >>= 1) {
            v1 += __shfl_down_sync(0xffffffffu, v1, off);
            v2 += __shfl_down_sync(0xffffffffu, v2, off);
        }
        if (tid == 0) { out[OFF_AS] = v1 / (float)BB; out[OFF_AST] = v2 / (float)BB; }
    }

    if (tid < NG) red[tid] = g_gflow[b * NG + tid];
    __syncthreads();
    if (tid == 0) {
        float m = 0.f;
        for (int i = 0; i < NG; i++) m += red[i];
        m /= (float)NG;
        float v = 0.f;
        for (int i = 0; i < NG; i++) { float d = red[i] - m; v += d * d; }
        float sd = fmaxf(sqrtf(v / 63.f), 1e-6f);
        sms[0] = m; sms[1] = sd;
    }
    __syncthreads();
    if (tid < NG) sng[tid] = (red[tid] - sms[0]) / sms[1];
    __syncthreads();

    float lv = local[b * PP + tid];
    red[tid] = lv; if (tid < 448) red[PP + tid] = 0.f;
    __syncthreads();
    for (int st = 512; st >= 1; st >>= 1) {
        if (tid < st) red[tid] += red[tid + st];
        __syncthreads();
    }
    float lmean = red[0] / (float)PP;
    __syncthreads();
    float dlv = lv - lmean;
    red[tid] = dlv * dlv; if (tid < 448) red[PP + tid] = 0.f;
    __syncthreads();
    for (int st = 512; st >= 1; st >>= 1) {
        if (tid < st) red[tid] += red[tid + st];
        __syncthreads();
    }
    float lstd = fmaxf(sqrtf(red[0] / 575.f), 1e-6f);
    __syncthreads();
    float nloc = dlv / lstd;

    int gid = ((tid / 24) / 3) * 8 + ((tid % 24) / 3);
    float gs = sng[gid];
    float ts = gs + 0.5f * nloc;
    out[OFF_GID + b * PP + tid] = (float)gid;
    out[OFF_GS  + b * PP + tid] = gs;
    sts[tid] = ts;
    sc[tid] = ts; if (tid < 448) sc[PP + tid] = -3.4e38f;
    if (tid == 0) scnt = 0;
    __syncthreads();
    for (int k = 2; k <= 1024; k <<= 1)
        for (int j = k >> 1; j > 0; j >>= 1) {
            for (int i = tid; i < 1024; i += 576) {
                int ixj = i ^ j;
                if (ixj > i) {
                    float x = sc[i], y = sc[ixj];
                    if (((i & k) == 0) == (x > y)) { sc[i] = y; sc[ixj] = x; }
                }
            }
            __syncthreads();
        }
    float thr = sc[1024 - 288];
    int m = (ts > thr) ? 1 : 0;
    if (m) atomicAdd(&scnt, 1);
    smask[tid] = (unsigned char)m;
    __syncthreads();
    if (tid == 0) {
        int rem = 288 - scnt;
        for (int t = 0; t < PP && rem > 0; t++)
            if (!smask[t] && sts[t] == thr) { smask[t] = 1; rem--; }
    }
    __syncthreads();
    float mv = smask[tid] ? 1.f : 0.f;
    out[OFF_PKEEP + b * PP + tid] = mv;
    out[OFF_KEEP + b * (PP + 1) + 1 + tid] = mv;
    if (tid == 0) out[OFF_KEEP + b * (PP + 1)] = 1.f;
}

// ============ launcher ====================================================
extern "C" void kernel_launch(void* const* d_in, const int* in_sizes, int n_in,
                              void* d_out, int out_size) {
    (void)in_sizes; (void)n_in; (void)out_size;
    const float* tokens = (const float*)d_in[0];
    const float* cls    = (const float*)d_in[1];
    const float* Wm     = (const float*)d_in[2];
    const float* local  = (const float*)d_in[3];
    float* out = (float*)d_out;

    k_nodes<<<dim3(NN, BB), 192>>>(tokens, cls);
    k_gemm <<<dim3(65, 6), 256>>>(Wm);
    k_gram <<<dim3(BB, 6), 169>>>();
    k_dyn  <<<BB, 416>>>(out);
    k_post <<<BB, 576>>>(local, out);
}